// round 3
// baseline (speedup 1.0000x reference)
#include <cuda_runtime.h>

static constexpr int NN = 100000;   // nodes
static constexpr int D  = 64;       // feature dim
static constexpr int NE = 1000000;  // edges

static constexpr int SCAN_T = 512;
static constexpr int NSCB   = (NN + SCAN_T - 1) / SCAN_T;   // 196

// Scratch (device globals — no allocation allowed)
__device__ float g_h2 [NN * D];   // dinv[row] * (x @ W)
__device__ float g_x  [NN * D];   // layer activations
__device__ float g_dinv[NN];
__device__ int   g_degi[NN];
__device__ int   g_off [NN + 1];
__device__ int   g_cur [NN];
__device__ int   g_scan[NN];
__device__ int   g_bsum[NSCB];
__device__ int   g_csr [NE];      // src ids grouped by dst
__device__ int   g_is64;

// ---------------------------------------------------------------------------
// Fused: zero degree counters + detect int64 vs int32 edge index.
// For int64 little-endian values < 2^17, every odd 32-bit word is 0.
__global__ void init_kernel(const int* __restrict__ w) {
    int i = blockIdx.x * 256 + threadIdx.x;
    if (i < NN) g_degi[i] = 0;
    if (blockIdx.x == 0) {
        __shared__ int s;
        if (threadIdx.x == 0) s = 0;
        __syncthreads();
        int v = 0;
        for (int j = threadIdx.x; j < 4096; j += 256) v |= w[2 * j + 1];
        if (v) atomicOr(&s, 1);
        __syncthreads();
        if (threadIdx.x == 0) g_is64 = (s == 0) ? 1 : 0;
    }
}

__device__ __forceinline__ int edge_at(const void* ei, long long pos) {
    if (g_is64) return (int)((const long long*)ei)[pos];
    return ((const int*)ei)[pos];
}

__global__ void degi_count(const void* __restrict__ ei) {
    int e = blockIdx.x * 256 + threadIdx.x;
    if (e < NE) atomicAdd(&g_degi[edge_at(ei, (long long)NE + e)], 1);
}

// ---- prefix scan (3 kernels) ----------------------------------------------
__global__ void scan1() {
    __shared__ int s[SCAN_T];
    int i = blockIdx.x * SCAN_T + threadIdx.x;
    int v = (i < NN) ? g_degi[i] : 0;
    s[threadIdx.x] = v;
    __syncthreads();
    #pragma unroll
    for (int off = 1; off < SCAN_T; off <<= 1) {
        int t = (threadIdx.x >= off) ? s[threadIdx.x - off] : 0;
        __syncthreads();
        s[threadIdx.x] += t;
        __syncthreads();
    }
    if (i < NN) g_scan[i] = s[threadIdx.x];
    if (threadIdx.x == SCAN_T - 1) g_bsum[blockIdx.x] = s[threadIdx.x];
}

__global__ void scan2() {   // one block of 256 threads; NSCB=196 <= 256
    __shared__ int s[256];
    int v = (threadIdx.x < NSCB) ? g_bsum[threadIdx.x] : 0;
    s[threadIdx.x] = v;
    __syncthreads();
    #pragma unroll
    for (int off = 1; off < 256; off <<= 1) {
        int t = (threadIdx.x >= off) ? s[threadIdx.x - off] : 0;
        __syncthreads();
        s[threadIdx.x] += t;
        __syncthreads();
    }
    if (threadIdx.x < NSCB) g_bsum[threadIdx.x] = s[threadIdx.x];
}

// Fused: exclusive offsets + cursor init + dinv (rsqrt of degree+selfloop)
__global__ void scan3() {
    int i = blockIdx.x * 256 + threadIdx.x;
    if (i >= NN) return;
    int b = i / SCAN_T;
    int di = g_degi[i];
    int incl = g_scan[i] + (b > 0 ? g_bsum[b - 1] : 0);
    g_off[i + 1] = incl;
    if (i == 0) g_off[0] = 0;
    g_cur[i] = incl - di;
    g_dinv[i] = rsqrtf(1.0f + (float)di);
}

__global__ void csr_fill(const void* __restrict__ ei) {
    int e = blockIdx.x * 256 + threadIdx.x;
    if (e >= NE) return;
    int src = edge_at(ei, e);
    int dst = edge_at(ei, (long long)NE + e);
    int pos = atomicAdd(&g_cur[dst], 1);
    g_csr[pos] = src;
}

// ---------------------------------------------------------------------------
// Y[row] = (bias? + ) (scale? dinv[row] : 1) * (X[row] @ W)   (64x64 W)
// FFMA2 (fma.rn.f32x2) mainloop: accumulators are column-pairs in 64-bit regs.
//  - W pairs: contiguous cols in smem -> free via LDS.128 reinterpret.
//  - X broadcast pairs {a,a}: stored DUPLICATED in smem -> single LDS.64,
//    address independent of column-thread -> broadcast, conflict-free.
static constexpr int XD_STRIDE = 130;  // 128 + 2 pad (even -> 8B-aligned LDS.64)

__global__ void __launch_bounds__(256) gemm64(
        const float* __restrict__ X, const float* __restrict__ W,
        const float* __restrict__ bias, int use_scale,
        float* __restrict__ Y) {
    __shared__ float xd[64 * XD_STRIDE];   // xd[row*130 + 2k] = xd[.. +1] = X[row][k]
    __shared__ float ws[64 * 64];
    const int tid  = threadIdx.x;
    const int base = blockIdx.x * 64;

    #pragma unroll
    for (int i = 0; i < 4; i++) {
        int idx = tid + i * 256;
        ((float4*)ws)[idx] = ((const float4*)W)[idx];
    }
    #pragma unroll
    for (int i = 0; i < 4; i++) {
        int idx  = tid + i * 256;     // float4 index within 64x16 tile
        int row  = idx >> 4;
        int col4 = idx & 15;
        float4 v = make_float4(0.f, 0.f, 0.f, 0.f);
        if (base + row < NN)
            v = ((const float4*)X)[(long long)(base + row) * 16 + col4];
        float* p = &xd[row * XD_STRIDE + col4 * 8];
        p[0] = v.x; p[1] = v.x;
        p[2] = v.y; p[3] = v.y;
        p[4] = v.z; p[5] = v.z;
        p[6] = v.w; p[7] = v.w;
    }
    __syncthreads();

    const int r0 = (tid >> 4) << 2;     // 4 rows per thread
    const int c0 = (tid & 15) << 2;     // 4 cols per thread (2 pairs)
    unsigned long long acc[4][2];
    #pragma unroll
    for (int i = 0; i < 4; i++) { acc[i][0] = 0ull; acc[i][1] = 0ull; }

    #pragma unroll 8
    for (int k = 0; k < 64; k++) {
        // {W[k][c0],W[k][c0+1]} and {W[k][c0+2],W[k][c0+3]} as packed pairs
        ulonglong2 wp = *(const ulonglong2*)&ws[k * 64 + c0];
        #pragma unroll
        for (int i = 0; i < 4; i++) {
            unsigned long long a =
                *(const unsigned long long*)&xd[(r0 + i) * XD_STRIDE + 2 * k];
            asm("fma.rn.f32x2 %0, %2, %3, %0;\n\t"
                "fma.rn.f32x2 %1, %2, %4, %1;"
                : "+l"(acc[i][0]), "+l"(acc[i][1])
                : "l"(a), "l"(wp.x), "l"(wp.y));
        }
    }

    #pragma unroll
    for (int i = 0; i < 4; i++) {
        int row = base + r0 + i;
        if (row < NN) {
            float4 o;
            ((unsigned long long*)&o)[0] = acc[i][0];
            ((unsigned long long*)&o)[1] = acc[i][1];
            float s = use_scale ? g_dinv[row] : 1.0f;
            o.x *= s; o.y *= s; o.z *= s; o.w *= s;
            if (bias) {
                o.x += bias[c0 + 0];
                o.y += bias[c0 + 1];
                o.z += bias[c0 + 2];
                o.w += bias[c0 + 3];
            }
            ((float4*)Y)[(long long)row * 16 + (c0 >> 2)] = o;
        }
    }
}

// ---------------------------------------------------------------------------
// CSR gather + fused epilogue: x'[v] = relu(dinv[v]*(h2[v] + sum_nb h2[src]) + b)
// 16 threads per node, one float4 lane each.
__global__ void __launch_bounds__(256) gather_epi(const float* __restrict__ bias) {
    int t    = blockIdx.x * 256 + threadIdx.x;
    int node = t >> 4;
    if (node >= NN) return;
    int lane = t & 15;

    const float4* __restrict__ h2 = (const float4*)g_h2;
    int beg = g_off[node];
    int end = g_off[node + 1];

    float4 a = h2[node * 16 + lane];    // self-loop term (already dinv[v]-scaled)

    int e = beg;
    for (; e + 1 < end; e += 2) {
        int s0 = __ldg(&g_csr[e]);
        int s1 = __ldg(&g_csr[e + 1]);
        float4 v0 = h2[s0 * 16 + lane];
        float4 v1 = h2[s1 * 16 + lane];
        a.x += v0.x + v1.x;
        a.y += v0.y + v1.y;
        a.z += v0.z + v1.z;
        a.w += v0.w + v1.w;
    }
    if (e < end) {
        int s0 = __ldg(&g_csr[e]);
        float4 v0 = h2[s0 * 16 + lane];
        a.x += v0.x; a.y += v0.y; a.z += v0.z; a.w += v0.w;
    }

    float dv = g_dinv[node];
    float4 o;
    o.x = fmaxf(fmaf(dv, a.x, bias[lane * 4 + 0]), 0.f);
    o.y = fmaxf(fmaf(dv, a.y, bias[lane * 4 + 1]), 0.f);
    o.z = fmaxf(fmaf(dv, a.z, bias[lane * 4 + 2]), 0.f);
    o.w = fmaxf(fmaf(dv, a.w, bias[lane * 4 + 3]), 0.f);
    ((float4*)g_x)[t] = o;
}

// ---------------------------------------------------------------------------
extern "C" void kernel_launch(void* const* d_in, const int* in_sizes, int n_in,
                              void* d_out, int out_size) {
    const float* x    = (const float*)d_in[0];
    const void*  ei   = d_in[1];
    const float* Ws   = (const float*)d_in[2];
    const float* bs   = (const float*)d_in[3];
    const float* Wout = (const float*)d_in[4];
    const float* bout = (const float*)d_in[5];
    float* out = (float*)d_out;

    float *h2p, *xp;
    cudaGetSymbolAddress((void**)&h2p, g_h2);
    cudaGetSymbolAddress((void**)&xp,  g_x);

    const int GB_N  = (NN + 255) / 256;
    const int GB_E  = (NE + 255) / 256;
    const int GB_MM = (NN + 63) / 64;
    const int GB_G  = (NN * 16 + 255) / 256;

    init_kernel<<<GB_N, 256>>>((const int*)ei);
    degi_count<<<GB_E, 256>>>(ei);
    scan1<<<NSCB, SCAN_T>>>();
    scan2<<<1, 256>>>();
    scan3<<<GB_N, 256>>>();
    csr_fill<<<GB_E, 256>>>(ei);

    const float* cur = x;
    for (int l = 0; l < 3; l++) {
        gemm64<<<GB_MM, 256>>>(cur, Ws + l * D * D, nullptr, 1, h2p);
        gather_epi<<<GB_G, 256>>>(bs + l * D);
        cur = xp;
    }
    gemm64<<<GB_MM, 256>>>(cur, Wout, bout, 0, out);
}

// round 4
// speedup vs baseline: 1.1591x; 1.1591x over previous
#include <cuda_runtime.h>

static constexpr int NN = 100000;   // nodes
static constexpr int D  = 64;       // feature dim
static constexpr int NE = 1000000;  // edges

static constexpr int SCAN_T = 512;
static constexpr int NSCB   = (NN + SCAN_T - 1) / SCAN_T;   // 196

// Scratch (device globals — no allocation allowed)
__device__ float g_h2 [NN * D];   // dinv[row] * (x @ W)
__device__ float g_x  [NN * D];   // layer activations
__device__ float g_dinv[NN];
__device__ int   g_degi[NN];      // zero at entry (BSS first call; csr_fill re-zeros)
__device__ int   g_off [NN + 1];
__device__ int   g_cur [NN];
__device__ int   g_scan[NN];
__device__ int   g_bsum[NSCB];
__device__ int   g_csr [NE];      // src ids grouped by dst
__device__ int   g_is64;

// ---------------------------------------------------------------------------
// Detect int64 vs int32 edge index (JAX may silently downcast).
// For int64 little-endian values < 2^17, every odd 32-bit word is 0.
__global__ void detect_kernel(const int* __restrict__ w) {
    __shared__ int s;
    if (threadIdx.x == 0) s = 0;
    __syncthreads();
    int v = 0;
    for (int j = threadIdx.x; j < 4096; j += 256) v |= w[2 * j + 1];
    if (v) atomicOr(&s, 1);
    __syncthreads();
    if (threadIdx.x == 0) g_is64 = (s == 0) ? 1 : 0;
}

__device__ __forceinline__ int edge_at(const void* ei, long long pos) {
    if (g_is64) return (int)((const long long*)ei)[pos];
    return ((const int*)ei)[pos];
}

__global__ void degi_count(const void* __restrict__ ei) {
    int e = blockIdx.x * 256 + threadIdx.x;
    if (e < NE) atomicAdd(&g_degi[edge_at(ei, (long long)NE + e)], 1);
}

// ---- prefix scan (2 kernels) ----------------------------------------------
__global__ void scan1() {
    __shared__ int s[SCAN_T];
    int i = blockIdx.x * SCAN_T + threadIdx.x;
    int v = (i < NN) ? g_degi[i] : 0;
    s[threadIdx.x] = v;
    __syncthreads();
    #pragma unroll
    for (int off = 1; off < SCAN_T; off <<= 1) {
        int t = (threadIdx.x >= off) ? s[threadIdx.x - off] : 0;
        __syncthreads();
        s[threadIdx.x] += t;
        __syncthreads();
    }
    if (i < NN) g_scan[i] = s[threadIdx.x];
    if (threadIdx.x == SCAN_T - 1) g_bsum[blockIdx.x] = s[threadIdx.x];
}

// Fused: per-block re-scan of the 196 block sums + offsets + cursor + dinv.
__global__ void scan23() {
    __shared__ int bs[256];
    int v = (threadIdx.x < NSCB) ? g_bsum[threadIdx.x] : 0;
    bs[threadIdx.x] = v;
    __syncthreads();
    #pragma unroll
    for (int off = 1; off < 256; off <<= 1) {
        int t = (threadIdx.x >= off) ? bs[threadIdx.x - off] : 0;
        __syncthreads();
        bs[threadIdx.x] += t;
        __syncthreads();
    }
    int i = blockIdx.x * 256 + threadIdx.x;
    if (i >= NN) return;
    int b  = i / SCAN_T;
    int di = g_degi[i];
    int incl = g_scan[i] + (b > 0 ? bs[b - 1] : 0);
    g_off[i + 1] = incl;
    if (i == 0) g_off[0] = 0;
    g_cur[i] = incl - di;
    g_dinv[i] = rsqrtf(1.0f + (float)di);
}

// Fill CSR; also re-zero g_degi so the NEXT invocation starts clean.
__global__ void csr_fill(const void* __restrict__ ei) {
    int e = blockIdx.x * 256 + threadIdx.x;
    if (e < NN) g_degi[e] = 0;
    if (e >= NE) return;
    int src = edge_at(ei, e);
    int dst = edge_at(ei, (long long)NE + e);
    int pos = atomicAdd(&g_cur[dst], 1);
    g_csr[pos] = src;
}

// ---------------------------------------------------------------------------
// Y[row] = (bias? + ) (scale? dinv[row] : 1) * (X[row] @ W)   (64x64 W)
//
// k-pair FFMA2 mainloop: accumulate with fma.rn.f32x2 over K-pairs:
//   acc[i][j] (2x f32) += {x[r][2k], x[r][2k+1]} * {W[2k][c], W[2k+1][c]}
// horizontal add at the end. A-pairs are contiguous in row-major xs (LDS.64,
// broadcast across the 16 column-threads). W-pairs need W transposed in smem:
// wt64[c*33 + kp] = {W[2kp][c], W[2kp+1][c]} (stride 33 u64 => bank-pair
// (2c+2kp) mod 32, conflict-free for c = lane&15). Columns are mapped
// stride-16: thread covers cols {c0, c0+16, c0+32, c0+48}.
static constexpr int WT_STRIDE = 33;   // in ulonglong units

__global__ void __launch_bounds__(256) gemm64(
        const float* __restrict__ X, const float* __restrict__ W,
        const float* __restrict__ bias, int use_scale,
        float* __restrict__ Y) {
    __shared__ float xs[64 * 64];
    __shared__ unsigned long long wt64[64 * WT_STRIDE];
    float* wtf = (float*)wt64;            // wtf[c*66 + k] = W[k][c]
    const int tid  = threadIdx.x;
    const int base = blockIdx.x * 64;

    // load W transposed
    #pragma unroll
    for (int i = 0; i < 4; i++) {
        int idx  = tid + i * 256;         // float4 index in row-major W
        int k    = idx >> 4;
        int c    = (idx & 15) * 4;
        float4 v = ((const float4*)W)[idx];
        wtf[(c + 0) * 66 + k] = v.x;
        wtf[(c + 1) * 66 + k] = v.y;
        wtf[(c + 2) * 66 + k] = v.z;
        wtf[(c + 3) * 66 + k] = v.w;
    }
    // load X tile (64 rows x 64 cols), zero-pad tail rows
    #pragma unroll
    for (int i = 0; i < 4; i++) {
        int idx  = tid + i * 256;
        int row  = idx >> 4;
        int col4 = idx & 15;
        float4 v = make_float4(0.f, 0.f, 0.f, 0.f);
        if (base + row < NN)
            v = ((const float4*)X)[(long long)(base + row) * 16 + col4];
        ((float4*)xs)[idx] = v;
    }
    __syncthreads();

    const int r0 = (tid >> 4) << 2;       // 4 rows per thread
    const int c0 = tid & 15;              // cols c0 + 16*j
    unsigned long long acc[4][4];
    #pragma unroll
    for (int i = 0; i < 4; i++)
        #pragma unroll
        for (int j = 0; j < 4; j++) acc[i][j] = 0ull;

    #pragma unroll 8
    for (int kp = 0; kp < 32; kp++) {
        unsigned long long a[4], w[4];
        #pragma unroll
        for (int i = 0; i < 4; i++)
            a[i] = *(const unsigned long long*)&xs[(r0 + i) * 64 + 2 * kp];
        #pragma unroll
        for (int j = 0; j < 4; j++)
            w[j] = wt64[(c0 + 16 * j) * WT_STRIDE + kp];
        #pragma unroll
        for (int i = 0; i < 4; i++)
            #pragma unroll
            for (int j = 0; j < 4; j++)
                asm("fma.rn.f32x2 %0, %1, %2, %0;"
                    : "+l"(acc[i][j]) : "l"(a[i]), "l"(w[j]));
    }

    #pragma unroll
    for (int i = 0; i < 4; i++) {
        int row = base + r0 + i;
        if (row >= NN) continue;
        float s = use_scale ? g_dinv[row] : 1.0f;
        #pragma unroll
        for (int j = 0; j < 4; j++) {
            float lo, hi;
            asm("mov.b64 {%0, %1}, %2;" : "=f"(lo), "=f"(hi) : "l"(acc[i][j]));
            float r = (lo + hi) * s;
            int c = c0 + 16 * j;
            if (bias) r += bias[c];
            Y[(long long)row * 64 + c] = r;
        }
    }
}

// ---------------------------------------------------------------------------
// CSR gather + fused epilogue: x'[v] = relu(dinv[v]*(h2[v] + sum_nb h2[src]) + b)
// 16 threads per node, one float4 lane each.
__global__ void __launch_bounds__(256) gather_epi(const float* __restrict__ bias) {
    int t    = blockIdx.x * 256 + threadIdx.x;
    int node = t >> 4;
    if (node >= NN) return;
    int lane = t & 15;

    const float4* __restrict__ h2 = (const float4*)g_h2;
    int beg = g_off[node];
    int end = g_off[node + 1];

    float4 a = h2[node * 16 + lane];    // self-loop term (already dinv[v]-scaled)

    int e = beg;
    for (; e + 1 < end; e += 2) {
        int s0 = __ldg(&g_csr[e]);
        int s1 = __ldg(&g_csr[e + 1]);
        float4 v0 = h2[s0 * 16 + lane];
        float4 v1 = h2[s1 * 16 + lane];
        a.x += v0.x + v1.x;
        a.y += v0.y + v1.y;
        a.z += v0.z + v1.z;
        a.w += v0.w + v1.w;
    }
    if (e < end) {
        int s0 = __ldg(&g_csr[e]);
        float4 v0 = h2[s0 * 16 + lane];
        a.x += v0.x; a.y += v0.y; a.z += v0.z; a.w += v0.w;
    }

    float dv = g_dinv[node];
    float4 o;
    o.x = fmaxf(fmaf(dv, a.x, bias[lane * 4 + 0]), 0.f);
    o.y = fmaxf(fmaf(dv, a.y, bias[lane * 4 + 1]), 0.f);
    o.z = fmaxf(fmaf(dv, a.z, bias[lane * 4 + 2]), 0.f);
    o.w = fmaxf(fmaf(dv, a.w, bias[lane * 4 + 3]), 0.f);
    ((float4*)g_x)[t] = o;
}

// ---------------------------------------------------------------------------
extern "C" void kernel_launch(void* const* d_in, const int* in_sizes, int n_in,
                              void* d_out, int out_size) {
    const float* x    = (const float*)d_in[0];
    const void*  ei   = d_in[1];
    const float* Ws   = (const float*)d_in[2];
    const float* bs   = (const float*)d_in[3];
    const float* Wout = (const float*)d_in[4];
    const float* bout = (const float*)d_in[5];
    float* out = (float*)d_out;

    float *h2p, *xp;
    cudaGetSymbolAddress((void**)&h2p, g_h2);
    cudaGetSymbolAddress((void**)&xp,  g_x);

    const int GB_N  = (NN + 255) / 256;
    const int GB_E  = (NE + 255) / 256;
    const int GB_MM = (NN + 63) / 64;
    const int GB_G  = (NN * 16 + 255) / 256;

    detect_kernel<<<1, 256>>>((const int*)ei);
    degi_count<<<GB_E, 256>>>(ei);
    scan1<<<NSCB, SCAN_T>>>();
    scan23<<<GB_N, 256>>>();
    csr_fill<<<GB_E, 256>>>(ei);

    const float* cur = x;
    for (int l = 0; l < 3; l++) {
        gemm64<<<GB_MM, 256>>>(cur, Ws + l * D * D, nullptr, 1, h2p);
        gather_epi<<<GB_G, 256>>>(bs + l * D);
        cur = xp;
    }
    gemm64<<<GB_MM, 256>>>(cur, Wout, bout, 0, out);
}

// round 6
// speedup vs baseline: 1.3855x; 1.1953x over previous
#include <cuda_runtime.h>
#include <cuda_bf16.h>
#include <cstdint>

static constexpr int NN = 100000;   // nodes
static constexpr int D  = 64;       // feature dim
static constexpr int NE = 1000000;  // edges

static constexpr int SCAN_T = 512;
static constexpr int NSCB   = (NN + SCAN_T - 1) / SCAN_T;   // 196

// Scratch (device globals — no allocation allowed)
__device__ float g_h2 [NN * D];   // dinv[row] * (x @ W)
__device__ float g_x  [NN * D];   // layer activations
__device__ float g_dinv[NN];
__device__ int   g_degi[NN];      // zero at entry (BSS first call; csr_fill re-zeros)
__device__ int   g_off [NN + 1];
__device__ int   g_cur [NN];
__device__ int   g_scan[NN];
__device__ int   g_bsum[NSCB];
__device__ int   g_csr [NE];      // src ids grouped by dst
__device__ int   g_is64;

// ---------------------------------------------------------------------------
// Detect int64 vs int32 edge index (JAX may silently downcast).
// For int64 little-endian values < 2^17, every odd 32-bit word is 0.
__global__ void detect_kernel(const int* __restrict__ w) {
    __shared__ int s;
    if (threadIdx.x == 0) s = 0;
    __syncthreads();
    int v = 0;
    for (int j = threadIdx.x; j < 4096; j += 256) v |= w[2 * j + 1];
    if (v) atomicOr(&s, 1);
    __syncthreads();
    if (threadIdx.x == 0) g_is64 = (s == 0) ? 1 : 0;
}

__device__ __forceinline__ int edge_at(const void* ei, long long pos) {
    if (g_is64) return (int)((const long long*)ei)[pos];
    return ((const int*)ei)[pos];
}

__global__ void degi_count(const void* __restrict__ ei) {
    int e = blockIdx.x * 256 + threadIdx.x;
    if (e < NE) atomicAdd(&g_degi[edge_at(ei, (long long)NE + e)], 1);
}

// ---- prefix scan ----------------------------------------------------------
__global__ void scan1() {
    __shared__ int s[SCAN_T];
    int i = blockIdx.x * SCAN_T + threadIdx.x;
    int v = (i < NN) ? g_degi[i] : 0;
    s[threadIdx.x] = v;
    __syncthreads();
    #pragma unroll
    for (int off = 1; off < SCAN_T; off <<= 1) {
        int t = (threadIdx.x >= off) ? s[threadIdx.x - off] : 0;
        __syncthreads();
        s[threadIdx.x] += t;
        __syncthreads();
    }
    if (i < NN) g_scan[i] = s[threadIdx.x];
    if (threadIdx.x == SCAN_T - 1) g_bsum[blockIdx.x] = s[threadIdx.x];
}

// Fused: per-block re-scan of block sums + offsets + cursor + dinv.
__global__ void scan23() {
    __shared__ int bs[256];
    int v = (threadIdx.x < NSCB) ? g_bsum[threadIdx.x] : 0;
    bs[threadIdx.x] = v;
    __syncthreads();
    #pragma unroll
    for (int off = 1; off < 256; off <<= 1) {
        int t = (threadIdx.x >= off) ? bs[threadIdx.x - off] : 0;
        __syncthreads();
        bs[threadIdx.x] += t;
        __syncthreads();
    }
    int i = blockIdx.x * 256 + threadIdx.x;
    if (i >= NN) return;
    int b  = i / SCAN_T;
    int di = g_degi[i];
    int incl = g_scan[i] + (b > 0 ? bs[b - 1] : 0);
    g_off[i + 1] = incl;
    if (i == 0) g_off[0] = 0;
    g_cur[i] = incl - di;
    g_dinv[i] = rsqrtf(1.0f + (float)di);
}

// Fill CSR; also re-zero g_degi so the NEXT invocation starts clean.
__global__ void csr_fill(const void* __restrict__ ei) {
    int e = blockIdx.x * 256 + threadIdx.x;
    if (e < NN) g_degi[e] = 0;
    if (e >= NE) return;
    int src = edge_at(ei, e);
    int dst = edge_at(ei, (long long)NE + e);
    int pos = atomicAdd(&g_cur[dst], 1);
    g_csr[pos] = src;
}

// ---------------------------------------------------------------------------
// Tensor-core GEMM via mma.sync (sm_80 PTX -> HMMA on sm_103; no 'a' features):
//   Y[128 x 64] = epilogue( X[128 x 64] @ W[64 x 64] )
// bf16 3-pass error compensation: D = Ah Bh + Ah Bl + Al Bh  (fp32 accum).
// A: X tile hi/lo bf16, row-major [128][72] halves (144B stride: ldmatrix
//    phase addresses land on 8 distinct bank-quads -> conflict-free).
// B: W^T hi/lo bf16, [n][k] = [64][72] halves.
static constexpr int HSTR  = 72;   // halves per row (64 + 8 pad)
static constexpr int SM_AH = 0;
static constexpr int SM_AL = SM_AH + 128 * HSTR * 2;   // 18432
static constexpr int SM_BH = SM_AL + 128 * HSTR * 2;   // 36864
static constexpr int SM_BL = SM_BH + 64 * HSTR * 2;    // 46080
static constexpr int SM_TOT = SM_BL + 64 * HSTR * 2;   // 55296

__device__ __forceinline__ uint32_t smem_u32(const void* p) {
    uint32_t a;
    asm("{ .reg .u64 t; cvta.to.shared.u64 t, %1; cvt.u32.u64 %0, t; }"
        : "=r"(a) : "l"(p));
    return a;
}
__device__ __forceinline__ void ldsm4(uint32_t& r0, uint32_t& r1, uint32_t& r2,
                                      uint32_t& r3, uint32_t addr) {
    asm volatile("ldmatrix.sync.aligned.m8n8.x4.shared.b16 {%0,%1,%2,%3}, [%4];"
                 : "=r"(r0), "=r"(r1), "=r"(r2), "=r"(r3) : "r"(addr));
}
__device__ __forceinline__ void mma16816(float* c, const uint32_t* a,
                                         uint32_t b0, uint32_t b1) {
    asm volatile(
        "mma.sync.aligned.m16n8k16.row.col.f32.bf16.bf16.f32 "
        "{%0,%1,%2,%3}, {%4,%5,%6,%7}, {%8,%9}, {%0,%1,%2,%3};"
        : "+f"(c[0]), "+f"(c[1]), "+f"(c[2]), "+f"(c[3])
        : "r"(a[0]), "r"(a[1]), "r"(a[2]), "r"(a[3]), "r"(b0), "r"(b1));
}

__device__ __forceinline__ void split_bf16(float x, unsigned short& h, unsigned short& l) {
    __nv_bfloat16 hb = __float2bfloat16(x);
    __nv_bfloat16 lb = __float2bfloat16(x - __bfloat162float(hb));
    h = __bfloat16_as_ushort(hb);
    l = __bfloat16_as_ushort(lb);
}

__global__ void __launch_bounds__(256) gemm_tc(
        const float* __restrict__ X, const float* __restrict__ W,
        const float* __restrict__ bias, int use_scale,
        float* __restrict__ Y) {
    extern __shared__ char smem[];
    const int tid  = threadIdx.x;
    const int wid  = tid >> 5;
    const int lane = tid & 31;
    const long long base = (long long)blockIdx.x * 128;

    // ---- fill A (X tile 128x64 -> hi/lo halves) ----
    #pragma unroll
    for (int i = 0; i < 8; i++) {
        int idx  = tid + i * 256;          // float4 index, 2048 total
        int row  = idx >> 4;
        int k    = (idx & 15) * 4;
        float4 v = make_float4(0.f, 0.f, 0.f, 0.f);
        if (base + row < NN)
            v = ((const float4*)X)[(base + row) * 16 + (k >> 2)];
        unsigned short h0, l0, h1, l1, h2v, l2v, h3, l3;
        split_bf16(v.x, h0, l0); split_bf16(v.y, h1, l1);
        split_bf16(v.z, h2v, l2v); split_bf16(v.w, h3, l3);
        unsigned long long hp = (unsigned long long)h0
            | ((unsigned long long)h1 << 16) | ((unsigned long long)h2v << 32)
            | ((unsigned long long)h3 << 48);
        unsigned long long lp = (unsigned long long)l0
            | ((unsigned long long)l1 << 16) | ((unsigned long long)l2v << 32)
            | ((unsigned long long)l3 << 48);
        uint32_t off = (uint32_t)(row * HSTR + k) * 2;
        *(unsigned long long*)(smem + SM_AH + off) = hp;
        *(unsigned long long*)(smem + SM_AL + off) = lp;
    }
    // ---- fill B (W^T: Bt[n][k] = W[k][n]) ----
    #pragma unroll
    for (int i = 0; i < 16; i++) {
        int idx = tid + i * 256;           // coalesced read of W
        int k = idx >> 6, n = idx & 63;
        unsigned short h, l;
        split_bf16(W[idx], h, l);
        uint32_t off = (uint32_t)(n * HSTR + k) * 2;
        *(unsigned short*)(smem + SM_BH + off) = h;
        *(unsigned short*)(smem + SM_BL + off) = l;
    }
    __syncthreads();

    const uint32_t sb = smem_u32(smem);
    const int r0w = wid * 16;              // warp's 16 output rows

    // ldmatrix per-lane addresses
    const int li  = lane >> 3;             // matrix index 0..3
    const int lw  = lane & 7;
    // A x4: m0(r0-7,k0-7) m1(r8-15,k0-7) m2(r0-7,k8-15) m3(r8-15,k8-15)
    const uint32_t a_off =
        (uint32_t)(((r0w + (li & 1) * 8 + lw) * HSTR + (li >> 1) * 8) * 2);
    // B x4: m0(n0,k0) m1(n0,k8) m2(n0+8,k0) m3(n0+8,k8)
    const uint32_t b_off =
        (uint32_t)((((li >> 1) * 8 + lw) * HSTR + (li & 1) * 8) * 2);

    float acc[8][4];
    #pragma unroll
    for (int nt = 0; nt < 8; nt++)
        #pragma unroll
        for (int q = 0; q < 4; q++) acc[nt][q] = 0.f;

    const uint32_t aBase[3] = { sb + SM_AH, sb + SM_AH, sb + SM_AL };
    const uint32_t bBase[3] = { sb + SM_BH, sb + SM_BL, sb + SM_BH };

    #pragma unroll
    for (int pass = 0; pass < 3; pass++) {
        #pragma unroll
        for (int kt = 0; kt < 4; kt++) {
            uint32_t a[4];
            ldsm4(a[0], a[1], a[2], a[3], aBase[pass] + a_off + kt * 32);
            #pragma unroll
            for (int ntp = 0; ntp < 4; ntp++) {
                uint32_t b0, b1, b2, b3;
                ldsm4(b0, b1, b2, b3,
                      bBase[pass] + b_off + (uint32_t)(ntp * 16 * HSTR * 2) + kt * 32);
                mma16816(acc[2 * ntp],     a, b0, b1);
                mma16816(acc[2 * ntp + 1], a, b2, b3);
            }
        }
    }

    // ---- epilogue ----
    // C frag m16n8: lane -> (row = lane/4 [+8 for c2,c3], col = (lane%4)*2)
    const int rA = r0w + (lane >> 2);
    const int rB = rA + 8;
    long long gA = base + rA, gB = base + rB;
    bool vA = gA < NN, vB = gB < NN;
    float sA = 1.f, sB = 1.f;
    if (use_scale) {
        if (vA) sA = g_dinv[gA];
        if (vB) sB = g_dinv[gB];
    }
    #pragma unroll
    for (int nt = 0; nt < 8; nt++) {
        int cg = nt * 8 + (lane & 3) * 2;
        float bx = 0.f, by = 0.f;
        if (bias) { bx = bias[cg]; by = bias[cg + 1]; }
        if (vA) {
            float2 o = make_float2(acc[nt][0] * sA + bx, acc[nt][1] * sA + by);
            *(float2*)&Y[gA * 64 + cg] = o;
        }
        if (vB) {
            float2 o = make_float2(acc[nt][2] * sB + bx, acc[nt][3] * sB + by);
            *(float2*)&Y[gB * 64 + cg] = o;
        }
    }
}

// ---------------------------------------------------------------------------
// CSR gather + fused epilogue: x'[v] = relu(dinv[v]*(h2[v] + sum_nb h2[src]) + b)
// 16 threads per node, one float4 lane each.
__global__ void __launch_bounds__(256) gather_epi(const float* __restrict__ bias) {
    int t    = blockIdx.x * 256 + threadIdx.x;
    int node = t >> 4;
    if (node >= NN) return;
    int lane = t & 15;

    const float4* __restrict__ h2 = (const float4*)g_h2;
    int beg = g_off[node];
    int end = g_off[node + 1];

    float4 a = h2[node * 16 + lane];    // self-loop term (already dinv[v]-scaled)

    int e = beg;
    for (; e + 1 < end; e += 2) {
        int s0 = __ldg(&g_csr[e]);
        int s1 = __ldg(&g_csr[e + 1]);
        float4 v0 = h2[s0 * 16 + lane];
        float4 v1 = h2[s1 * 16 + lane];
        a.x += v0.x + v1.x;
        a.y += v0.y + v1.y;
        a.z += v0.z + v1.z;
        a.w += v0.w + v1.w;
    }
    if (e < end) {
        int s0 = __ldg(&g_csr[e]);
        float4 v0 = h2[s0 * 16 + lane];
        a.x += v0.x; a.y += v0.y; a.z += v0.z; a.w += v0.w;
    }

    float dv = g_dinv[node];
    float4 o;
    o.x = fmaxf(fmaf(dv, a.x, bias[lane * 4 + 0]), 0.f);
    o.y = fmaxf(fmaf(dv, a.y, bias[lane * 4 + 1]), 0.f);
    o.z = fmaxf(fmaf(dv, a.z, bias[lane * 4 + 2]), 0.f);
    o.w = fmaxf(fmaf(dv, a.w, bias[lane * 4 + 3]), 0.f);
    ((float4*)g_x)[t] = o;
}

// ---------------------------------------------------------------------------
extern "C" void kernel_launch(void* const* d_in, const int* in_sizes, int n_in,
                              void* d_out, int out_size) {
    const float* x    = (const float*)d_in[0];
    const void*  ei   = d_in[1];
    const float* Ws   = (const float*)d_in[2];
    const float* bs   = (const float*)d_in[3];
    const float* Wout = (const float*)d_in[4];
    const float* bout = (const float*)d_in[5];
    float* out = (float*)d_out;

    float *h2p, *xp;
    cudaGetSymbolAddress((void**)&h2p, g_h2);
    cudaGetSymbolAddress((void**)&xp,  g_x);

    cudaFuncSetAttribute(gemm_tc, cudaFuncAttributeMaxDynamicSharedMemorySize, SM_TOT);

    const int GB_E  = (NE + 255) / 256;
    const int GB_N  = (NN + 255) / 256;
    const int GB_MM = (NN + 127) / 128;
    const int GB_G  = (NN * 16 + 255) / 256;

    detect_kernel<<<1, 256>>>((const int*)ei);
    degi_count<<<GB_E, 256>>>(ei);
    scan1<<<NSCB, SCAN_T>>>();
    scan23<<<GB_N, 256>>>();
    csr_fill<<<GB_E, 256>>>(ei);

    const float* cur = x;
    for (int l = 0; l < 3; l++) {
        gemm_tc<<<GB_MM, 256, SM_TOT>>>(cur, Ws + l * D * D, nullptr, 1, h2p);
        gather_epi<<<GB_G, 256>>>(bs + l * D);
        cur = xp;
    }
    gemm_tc<<<GB_MM, 256, SM_TOT>>>(cur, Wout, bout, 0, out);
}

// round 7
// speedup vs baseline: 1.4414x; 1.0403x over previous
#include <cuda_runtime.h>
#include <cuda_bf16.h>
#include <cstdint>

static constexpr int NN = 100000;   // nodes
static constexpr int D  = 64;       // feature dim
static constexpr int NE = 1000000;  // edges

static constexpr int SCAN_T = 512;
static constexpr int NSCB   = (NN + SCAN_T - 1) / SCAN_T;   // 196

// Scratch (device globals — no allocation allowed)
__device__ float g_h2 [NN * D];   // h = x @ W (unscaled)
__device__ float g_x  [NN * D];   // layer activations
__device__ float g_dinv[NN];
__device__ int   g_degi[NN];      // zero at entry (BSS first call; csr_fill re-zeros)
__device__ int   g_off [NN + 1];
__device__ int   g_cur [NN];
__device__ int   g_scan[NN];
__device__ int   g_bsum[NSCB];
__device__ int   g_csr [NE];      // src ids grouped by dst

// ---------------------------------------------------------------------------
// Per-block int64-vs-int32 detection (JAX may silently downcast edge_index).
// For int64 little-endian values < 2^17 every odd 32-bit word is 0; int32 data
// in [0,100000) has P(word==0) ~ 1e-5, so 64 consecutive zeros => int64.
__device__ __forceinline__ int block_detect64(const int* __restrict__ w) {
    __shared__ int s_flag;
    if (threadIdx.x == 0) s_flag = 0;
    __syncthreads();
    if (threadIdx.x < 64 && w[2 * threadIdx.x + 1]) atomicOr(&s_flag, 1);
    __syncthreads();
    return s_flag == 0;
}

__device__ __forceinline__ int edge_at(const void* ei, int is64, long long pos) {
    if (is64) return (int)((const long long*)ei)[pos];
    return ((const int*)ei)[pos];
}

__global__ void degi_count(const void* __restrict__ ei) {
    int is64 = block_detect64((const int*)ei);
    int e = blockIdx.x * 256 + threadIdx.x;
    if (e < NE) atomicAdd(&g_degi[edge_at(ei, is64, (long long)NE + e)], 1);
}

// ---- prefix scan ----------------------------------------------------------
__global__ void scan1() {
    __shared__ int s[SCAN_T];
    int i = blockIdx.x * SCAN_T + threadIdx.x;
    int v = (i < NN) ? g_degi[i] : 0;
    s[threadIdx.x] = v;
    __syncthreads();
    #pragma unroll
    for (int off = 1; off < SCAN_T; off <<= 1) {
        int t = (threadIdx.x >= off) ? s[threadIdx.x - off] : 0;
        __syncthreads();
        s[threadIdx.x] += t;
        __syncthreads();
    }
    if (i < NN) g_scan[i] = s[threadIdx.x];
    if (threadIdx.x == SCAN_T - 1) g_bsum[blockIdx.x] = s[threadIdx.x];
}

// Fused: per-block re-scan of block sums + offsets + cursor + dinv.
__global__ void scan23() {
    __shared__ int bs[256];
    int v = (threadIdx.x < NSCB) ? g_bsum[threadIdx.x] : 0;
    bs[threadIdx.x] = v;
    __syncthreads();
    #pragma unroll
    for (int off = 1; off < 256; off <<= 1) {
        int t = (threadIdx.x >= off) ? bs[threadIdx.x - off] : 0;
        __syncthreads();
        bs[threadIdx.x] += t;
        __syncthreads();
    }
    int i = blockIdx.x * 256 + threadIdx.x;
    if (i >= NN) return;
    int b  = i / SCAN_T;
    int di = g_degi[i];
    int incl = g_scan[i] + (b > 0 ? bs[b - 1] : 0);
    g_off[i + 1] = incl;
    if (i == 0) g_off[0] = 0;
    g_cur[i] = incl - di;
    g_dinv[i] = rsqrtf(1.0f + (float)di);
}

// Fill CSR; also re-zero g_degi so the NEXT invocation starts clean.
__global__ void csr_fill(const void* __restrict__ ei) {
    int is64 = block_detect64((const int*)ei);
    int e = blockIdx.x * 256 + threadIdx.x;
    if (e < NN) g_degi[e] = 0;
    if (e >= NE) return;
    int src = edge_at(ei, is64, e);
    int dst = edge_at(ei, is64, (long long)NE + e);
    int pos = atomicAdd(&g_cur[dst], 1);
    g_csr[pos] = src;
}

// ---------------------------------------------------------------------------
// Tensor-core GEMM via mma.sync (sm_80 PTX -> HMMA on sm_103):
//   Y[128 x 64] = X[128 x 64] @ W[64 x 64]  (+ bias if given)
// bf16 3-pass error compensation: D = Ah Bh + Ah Bl + Al Bh  (fp32 accum).
static constexpr int HSTR  = 72;   // halves per row (64 + 8 pad)
static constexpr int SM_AH = 0;
static constexpr int SM_AL = SM_AH + 128 * HSTR * 2;   // 18432
static constexpr int SM_BH = SM_AL + 128 * HSTR * 2;   // 36864
static constexpr int SM_BL = SM_BH + 64 * HSTR * 2;    // 46080
static constexpr int SM_TOT = SM_BL + 64 * HSTR * 2;   // 55296

__device__ __forceinline__ uint32_t smem_u32(const void* p) {
    uint32_t a;
    asm("{ .reg .u64 t; cvta.to.shared.u64 t, %1; cvt.u32.u64 %0, t; }"
        : "=r"(a) : "l"(p));
    return a;
}
__device__ __forceinline__ void ldsm4(uint32_t& r0, uint32_t& r1, uint32_t& r2,
                                      uint32_t& r3, uint32_t addr) {
    asm volatile("ldmatrix.sync.aligned.m8n8.x4.shared.b16 {%0,%1,%2,%3}, [%4];"
                 : "=r"(r0), "=r"(r1), "=r"(r2), "=r"(r3) : "r"(addr));
}
__device__ __forceinline__ void mma16816(float* c, const uint32_t* a,
                                         uint32_t b0, uint32_t b1) {
    asm volatile(
        "mma.sync.aligned.m16n8k16.row.col.f32.bf16.bf16.f32 "
        "{%0,%1,%2,%3}, {%4,%5,%6,%7}, {%8,%9}, {%0,%1,%2,%3};"
        : "+f"(c[0]), "+f"(c[1]), "+f"(c[2]), "+f"(c[3])
        : "r"(a[0]), "r"(a[1]), "r"(a[2]), "r"(a[3]), "r"(b0), "r"(b1));
}
__device__ __forceinline__ void split_bf16(float x, unsigned short& h, unsigned short& l) {
    __nv_bfloat16 hb = __float2bfloat16(x);
    __nv_bfloat16 lb = __float2bfloat16(x - __bfloat162float(hb));
    h = __bfloat16_as_ushort(hb);
    l = __bfloat16_as_ushort(lb);
}

__global__ void __launch_bounds__(256) gemm_tc(
        const float* __restrict__ X, const float* __restrict__ W,
        const float* __restrict__ bias, float* __restrict__ Y) {
    extern __shared__ char smem[];
    const int tid  = threadIdx.x;
    const int wid  = tid >> 5;
    const int lane = tid & 31;
    const long long base = (long long)blockIdx.x * 128;

    // ---- fill A (X tile 128x64 -> hi/lo halves) ----
    #pragma unroll
    for (int i = 0; i < 8; i++) {
        int idx  = tid + i * 256;          // float4 index, 2048 total
        int row  = idx >> 4;
        int k    = (idx & 15) * 4;
        float4 v = make_float4(0.f, 0.f, 0.f, 0.f);
        if (base + row < NN)
            v = ((const float4*)X)[(base + row) * 16 + (k >> 2)];
        unsigned short h0, l0, h1, l1, h2v, l2v, h3, l3;
        split_bf16(v.x, h0, l0); split_bf16(v.y, h1, l1);
        split_bf16(v.z, h2v, l2v); split_bf16(v.w, h3, l3);
        unsigned long long hp = (unsigned long long)h0
            | ((unsigned long long)h1 << 16) | ((unsigned long long)h2v << 32)
            | ((unsigned long long)h3 << 48);
        unsigned long long lp = (unsigned long long)l0
            | ((unsigned long long)l1 << 16) | ((unsigned long long)l2v << 32)
            | ((unsigned long long)l3 << 48);
        uint32_t off = (uint32_t)(row * HSTR + k) * 2;
        *(unsigned long long*)(smem + SM_AH + off) = hp;
        *(unsigned long long*)(smem + SM_AL + off) = lp;
    }
    // ---- fill B (W^T: Bt[n][k] = W[k][n]) ----
    #pragma unroll
    for (int i = 0; i < 16; i++) {
        int idx = tid + i * 256;           // coalesced read of W
        int k = idx >> 6, n = idx & 63;
        unsigned short h, l;
        split_bf16(W[idx], h, l);
        uint32_t off = (uint32_t)(n * HSTR + k) * 2;
        *(unsigned short*)(smem + SM_BH + off) = h;
        *(unsigned short*)(smem + SM_BL + off) = l;
    }
    __syncthreads();

    const uint32_t sb = smem_u32(smem);
    const int r0w = wid * 16;              // warp's 16 output rows

    const int li  = lane >> 3;             // ldmatrix matrix index 0..3
    const int lw  = lane & 7;
    const uint32_t a_off =
        (uint32_t)(((r0w + (li & 1) * 8 + lw) * HSTR + (li >> 1) * 8) * 2);
    const uint32_t b_off =
        (uint32_t)((((li >> 1) * 8 + lw) * HSTR + (li & 1) * 8) * 2);

    float acc[8][4];
    #pragma unroll
    for (int nt = 0; nt < 8; nt++)
        #pragma unroll
        for (int q = 0; q < 4; q++) acc[nt][q] = 0.f;

    const uint32_t aBase[3] = { sb + SM_AH, sb + SM_AH, sb + SM_AL };
    const uint32_t bBase[3] = { sb + SM_BH, sb + SM_BL, sb + SM_BH };

    #pragma unroll
    for (int pass = 0; pass < 3; pass++) {
        #pragma unroll
        for (int kt = 0; kt < 4; kt++) {
            uint32_t a[4];
            ldsm4(a[0], a[1], a[2], a[3], aBase[pass] + a_off + kt * 32);
            #pragma unroll
            for (int ntp = 0; ntp < 4; ntp++) {
                uint32_t b0, b1, b2, b3;
                ldsm4(b0, b1, b2, b3,
                      bBase[pass] + b_off + (uint32_t)(ntp * 16 * HSTR * 2) + kt * 32);
                mma16816(acc[2 * ntp],     a, b0, b1);
                mma16816(acc[2 * ntp + 1], a, b2, b3);
            }
        }
    }

    // ---- epilogue: C frag m16n8 lane mapping ----
    const int rA = r0w + (lane >> 2);
    const int rB = rA + 8;
    long long gA = base + rA, gB = base + rB;
    bool vA = gA < NN, vB = gB < NN;
    #pragma unroll
    for (int nt = 0; nt < 8; nt++) {
        int cg = nt * 8 + (lane & 3) * 2;
        float bx = 0.f, by = 0.f;
        if (bias) { bx = bias[cg]; by = bias[cg + 1]; }
        if (vA) {
            float2 o = make_float2(acc[nt][0] + bx, acc[nt][1] + by);
            *(float2*)&Y[gA * 64 + cg] = o;
        }
        if (vB) {
            float2 o = make_float2(acc[nt][2] + bx, acc[nt][3] + by);
            *(float2*)&Y[gB * 64 + cg] = o;
        }
    }
}

// ---------------------------------------------------------------------------
// CSR gather + fused epilogue (h unscaled):
//   x'[v] = relu( dinv[v] * ( dinv[v]*h[v] + sum_src dinv[s]*h[s] ) + b )
// 16 threads per node, one float4 lane each; 4x unrolled for MLP.
__global__ void __launch_bounds__(256) gather_epi(const float* __restrict__ bias) {
    int t    = blockIdx.x * 256 + threadIdx.x;
    int node = t >> 4;
    if (node >= NN) return;
    int lane = t & 15;

    const float4* __restrict__ h2 = (const float4*)g_h2;
    int beg = g_off[node];
    int end = g_off[node + 1];
    float dv = g_dinv[node];

    float4 hs = h2[node * 16 + lane];
    float4 a;
    a.x = dv * hs.x; a.y = dv * hs.y; a.z = dv * hs.z; a.w = dv * hs.w;

    int e = beg;
    for (; e + 3 < end; e += 4) {
        int s0 = __ldg(&g_csr[e]);
        int s1 = __ldg(&g_csr[e + 1]);
        int s2 = __ldg(&g_csr[e + 2]);
        int s3 = __ldg(&g_csr[e + 3]);
        float d0 = g_dinv[s0], d1 = g_dinv[s1], d2 = g_dinv[s2], d3 = g_dinv[s3];
        float4 v0 = h2[s0 * 16 + lane];
        float4 v1 = h2[s1 * 16 + lane];
        float4 v2 = h2[s2 * 16 + lane];
        float4 v3 = h2[s3 * 16 + lane];
        a.x = fmaf(d0, v0.x, fmaf(d1, v1.x, fmaf(d2, v2.x, fmaf(d3, v3.x, a.x))));
        a.y = fmaf(d0, v0.y, fmaf(d1, v1.y, fmaf(d2, v2.y, fmaf(d3, v3.y, a.y))));
        a.z = fmaf(d0, v0.z, fmaf(d1, v1.z, fmaf(d2, v2.z, fmaf(d3, v3.z, a.z))));
        a.w = fmaf(d0, v0.w, fmaf(d1, v1.w, fmaf(d2, v2.w, fmaf(d3, v3.w, a.w))));
    }
    for (; e < end; e++) {
        int s0 = __ldg(&g_csr[e]);
        float d0 = g_dinv[s0];
        float4 v0 = h2[s0 * 16 + lane];
        a.x = fmaf(d0, v0.x, a.x);
        a.y = fmaf(d0, v0.y, a.y);
        a.z = fmaf(d0, v0.z, a.z);
        a.w = fmaf(d0, v0.w, a.w);
    }

    float4 o;
    o.x = fmaxf(fmaf(dv, a.x, bias[lane * 4 + 0]), 0.f);
    o.y = fmaxf(fmaf(dv, a.y, bias[lane * 4 + 1]), 0.f);
    o.z = fmaxf(fmaf(dv, a.z, bias[lane * 4 + 2]), 0.f);
    o.w = fmaxf(fmaf(dv, a.w, bias[lane * 4 + 3]), 0.f);
    ((float4*)g_x)[t] = o;
}

// ---------------------------------------------------------------------------
extern "C" void kernel_launch(void* const* d_in, const int* in_sizes, int n_in,
                              void* d_out, int out_size) {
    const float* x    = (const float*)d_in[0];
    const void*  ei   = d_in[1];
    const float* Ws   = (const float*)d_in[2];
    const float* bs   = (const float*)d_in[3];
    const float* Wout = (const float*)d_in[4];
    const float* bout = (const float*)d_in[5];
    float* out = (float*)d_out;

    float *h2p, *xp;
    cudaGetSymbolAddress((void**)&h2p, g_h2);
    cudaGetSymbolAddress((void**)&xp,  g_x);

    cudaFuncSetAttribute(gemm_tc, cudaFuncAttributeMaxDynamicSharedMemorySize, SM_TOT);

    // Side stream + events, created once on the (uncaptured) correctness call.
    static cudaStream_t s2 = nullptr;
    static cudaEvent_t  ev_fork = nullptr, ev_g1 = nullptr;
    if (!s2) {
        cudaStreamCreateWithFlags(&s2, cudaStreamNonBlocking);
        cudaEventCreateWithFlags(&ev_fork, cudaEventDisableTiming);
        cudaEventCreateWithFlags(&ev_g1, cudaEventDisableTiming);
    }

    const int GB_E  = (NE + 255) / 256;
    const int GB_N  = (NN + 255) / 256;
    const int GB_MM = (NN + 127) / 128;
    const int GB_G  = (NN * 16 + 255) / 256;

    // Fork: GEMM-1 (independent of the CSR build) runs on s2.
    cudaEventRecord(ev_fork, 0);
    cudaStreamWaitEvent(s2, ev_fork, 0);
    gemm_tc<<<GB_MM, 256, SM_TOT, s2>>>(x, Ws, nullptr, h2p);
    cudaEventRecord(ev_g1, s2);

    // CSR build on the main stream.
    degi_count<<<GB_E, 256>>>(ei);
    scan1<<<NSCB, SCAN_T>>>();
    scan23<<<GB_N, 256>>>();
    csr_fill<<<GB_E, 256>>>(ei);

    // Join, then the serial layer chain.
    cudaStreamWaitEvent(0, ev_g1, 0);
    gather_epi<<<GB_G, 256>>>(bs);
    gemm_tc<<<GB_MM, 256, SM_TOT>>>(xp, Ws + 1 * D * D, nullptr, h2p);
    gather_epi<<<GB_G, 256>>>(bs + 1 * D);
    gemm_tc<<<GB_MM, 256, SM_TOT>>>(xp, Ws + 2 * D * D, nullptr, h2p);
    gather_epi<<<GB_G, 256>>>(bs + 2 * D);
    gemm_tc<<<GB_MM, 256, SM_TOT>>>(xp, Wout, bout, out);
}